// round 14
// baseline (speedup 1.0000x reference)
#include <cuda_runtime.h>
#include <cstdint>

#define BB 2
#define SS 2048
#define HID 1024
#define HEADS 16
#define DH 64
#define INNER 1024

#define LOG2E 1.4426950408889634f
#define QSCALE (LOG2E * 0.125f)

// Scratch (device globals — no allocation allowed)
__device__ float g_q[BB*HEADS*SS*DH];    // tf32-rounded, pre-scaled by log2e/8
__device__ float g_k[BB*HEADS*SS*DH];    // tf32-rounded
__device__ float g_v[BB*HEADS*SS*DH];    // tf32-rounded
__device__ float g_ctx[BB*SS*INNER];     // [b][s][h*64+d]

// ---------------------------------------------------------------------------
// helpers
// ---------------------------------------------------------------------------
__device__ __forceinline__ unsigned f2tf(float x) {
    unsigned r;
    asm("cvt.rna.tf32.f32 %0, %1;" : "=r"(r) : "f"(x));
    return r;
}
__device__ __forceinline__ float f2tf_f(float x) {
    return __uint_as_float(f2tf(x));
}
__device__ __forceinline__ float fexp2(float x) {
    float y;
    asm("ex2.approx.ftz.f32 %0, %1;" : "=f"(y) : "f"(x));
    return y;
}
__device__ __forceinline__ void mma_tf32(float* d, const unsigned* a,
                                         unsigned b0, unsigned b1, const float* c) {
    asm volatile(
        "mma.sync.aligned.m16n8k8.row.col.f32.tf32.tf32.f32 "
        "{%0,%1,%2,%3}, {%4,%5,%6,%7}, {%8,%9}, {%10,%11,%12,%13};\n"
        : "=f"(d[0]), "=f"(d[1]), "=f"(d[2]), "=f"(d[3])
        : "r"(a[0]), "r"(a[1]), "r"(a[2]), "r"(a[3]),
          "r"(b0), "r"(b1),
          "f"(c[0]), "f"(c[1]), "f"(c[2]), "f"(c[3]));
}
__device__ __forceinline__ void cpa16(void* smem_ptr, const void* gptr) {
    unsigned sa = (unsigned)__cvta_generic_to_shared(smem_ptr);
    asm volatile("cp.async.cg.shared.global [%0], [%1], 16;\n" :: "r"(sa), "l"(gptr));
}
__device__ __forceinline__ void cpa_commit() {
    asm volatile("cp.async.commit_group;\n");
}
template<int N>
__device__ __forceinline__ void cpa_wait() {
    asm volatile("cp.async.wait_group %0;\n" :: "n"(N));
}

// ---------------------------------------------------------------------------
// GEMM (round-10 champion, unchanged): C[4096][1024] = X @ W + bias.
// 128 threads (4 warps, 2x2), tile 128x128x16, double buffered, cvt at STS.
// MODE 1: qkv (scatter to [b][h][s][d]; epilogue rounds to tf32, z==0 scaled)
// MODE 0: out projection (row-major out)
// ---------------------------------------------------------------------------
#define GK 1024
#define GN 1024
#define LDA 20
#define LDB 136

template<int MODE>
__global__ __launch_bounds__(128)
void gemm_tf32_kernel(const float* __restrict__ X0, const float* __restrict__ X1,
                      const float* __restrict__ X2,
                      const float* __restrict__ W0, const float* __restrict__ W1,
                      const float* __restrict__ W2,
                      const float* __restrict__ bi0, const float* __restrict__ bi1,
                      const float* __restrict__ bi2,
                      float* __restrict__ out0)
{
    __shared__ unsigned As[2][128*LDA];
    __shared__ unsigned Bs[2][16*LDB];

    const float* X; const float* W; const float* bias; float* out;
    int z = 0;
    if (MODE == 1) {
        z = blockIdx.z;
        if (z == 0)      { X = X0; W = W0; bias = bi0; out = g_q; }
        else if (z == 1) { X = X1; W = W1; bias = bi1; out = g_k; }
        else             { X = X2; W = W2; bias = bi2; out = g_v; }
    } else {
        X = X0; W = W0; bias = bi0; out = out0;
    }

    const int tid = threadIdx.x;
    const int lane = tid & 31;
    const int warp = tid >> 5;
    const int g = lane >> 2;
    const int t = lane & 3;
    const int wm = warp >> 1;
    const int wn = warp & 1;

    const int m0 = blockIdx.y * 128;
    const int n0 = blockIdx.x * 128;

    const int rowA = tid >> 2;
    const int cA   = (tid & 3) * 4;
    const int rowB = tid >> 5;
    const int cB   = (tid & 31) * 4;

    float4 ra[4], rb[4];

    auto ldg_tile = [&](int kt) {
        const int k0 = kt * 16;
#pragma unroll
        for (int p = 0; p < 4; p++)
            ra[p] = *(const float4*)(X + (size_t)(m0 + rowA + p*32) * GK + k0 + cA);
#pragma unroll
        for (int p = 0; p < 4; p++)
            rb[p] = *(const float4*)(W + (size_t)(k0 + rowB + p*4) * GN + n0 + cB);
    };
    auto sts_tile = [&](int buf) {
#pragma unroll
        for (int p = 0; p < 4; p++) {
            uint4 u = make_uint4(f2tf(ra[p].x), f2tf(ra[p].y), f2tf(ra[p].z), f2tf(ra[p].w));
            *(uint4*)&As[buf][(rowA + p*32)*LDA + cA] = u;
        }
#pragma unroll
        for (int p = 0; p < 4; p++) {
            uint4 u = make_uint4(f2tf(rb[p].x), f2tf(rb[p].y), f2tf(rb[p].z), f2tf(rb[p].w));
            *(uint4*)&Bs[buf][(rowB + p*4)*LDB + cB] = u;
        }
    };

    float c[4][8][4];
#pragma unroll
    for (int mf = 0; mf < 4; mf++)
#pragma unroll
        for (int nf = 0; nf < 8; nf++)
#pragma unroll
            for (int i = 0; i < 4; i++) c[mf][nf][i] = 0.f;

    ldg_tile(0);
    sts_tile(0);
    __syncthreads();

    for (int kt = 0; kt < GK/16; kt++) {
        const int buf = kt & 1;
        if (kt < GK/16 - 1) ldg_tile(kt + 1);

        const unsigned* A_ = As[buf];
        const unsigned* B_ = Bs[buf];
#pragma unroll
        for (int ks = 0; ks < 2; ks++) {
            unsigned a[4][4];
#pragma unroll
            for (int mf = 0; mf < 4; mf++) {
                int base = (wm*64 + mf*16 + g)*LDA + ks*8 + t;
                a[mf][0] = A_[base];
                a[mf][1] = A_[base + 8*LDA];
                a[mf][2] = A_[base + 4];
                a[mf][3] = A_[base + 8*LDA + 4];
            }
            unsigned bf[8][2];
#pragma unroll
            for (int nf = 0; nf < 8; nf++) {
                int base = (ks*8 + t)*LDB + wn*64 + nf*8 + g;
                bf[nf][0] = B_[base];
                bf[nf][1] = B_[base + 4*LDB];
            }
#pragma unroll
            for (int mf = 0; mf < 4; mf++)
#pragma unroll
                for (int nf = 0; nf < 8; nf++)
                    mma_tf32(c[mf][nf], a[mf], bf[nf][0], bf[nf][1], c[mf][nf]);
        }

        if (kt < GK/16 - 1) {
            sts_tile((kt + 1) & 1);
            __syncthreads();
        }
    }

    // epilogue
#pragma unroll
    for (int mf = 0; mf < 4; mf++) {
        int r0 = m0 + wm*64 + mf*16 + g;
        int r1 = r0 + 8;
#pragma unroll
        for (int nf = 0; nf < 8; nf++) {
            int col = n0 + wn*64 + nf*8 + 2*t;
            float2 bs = *(const float2*)(bias + col);
            float v00 = c[mf][nf][0] + bs.x, v01 = c[mf][nf][1] + bs.y;
            float v10 = c[mf][nf][2] + bs.x, v11 = c[mf][nf][3] + bs.y;
            if (MODE == 1) {
                if (z == 0) { v00 *= QSCALE; v01 *= QSCALE; v10 *= QSCALE; v11 *= QSCALE; }
                v00 = f2tf_f(v00); v01 = f2tf_f(v01);
                v10 = f2tf_f(v10); v11 = f2tf_f(v11);
                int h = col >> 6, d = col & 63;
                int b0i = r0 >> 11, s0 = r0 & 2047;
                int b1i = r1 >> 11, s1 = r1 & 2047;
                *(float2*)(out + ((size_t)(b0i*HEADS + h)*SS + s0)*DH + d) = make_float2(v00, v01);
                *(float2*)(out + ((size_t)(b1i*HEADS + h)*SS + s1)*DH + d) = make_float2(v10, v11);
            } else {
                *(float2*)(out + (size_t)r0*GN + col) = make_float2(v00, v01);
                *(float2*)(out + (size_t)r1*GN + col) = make_float2(v10, v11);
            }
        }
    }
}

// ---------------------------------------------------------------------------
// Flash attention: tf32 mma, pre-rounded inputs, STATIC-MAX exp2 softmax
// (scores provably bounded |s·log2e| << 126, so fixed shift of 0 is safe and
// softmax is shift-invariant), cp.async double-buffered K/V; P reuses the
// consumed K stage buffer. Block: 128 threads (4 warps), 64 q-rows.
// grid: (S/64, HEADS, B). smem 71680 B -> 3 CTAs/SM.
// ---------------------------------------------------------------------------
#define LDK 68
#define LDV 72
#define KST (64*LDK)
#define VST (64*LDV)

__global__ __launch_bounds__(128)
void attn_tf32_kernel(const float* __restrict__ pb, const float* __restrict__ mask)
{
    extern __shared__ unsigned smx[];
    unsigned* Kst = smx;             // [2][64*LDK]
    unsigned* Vst = smx + 2*KST;     // [2][64*LDV]

    const int tid = threadIdx.x;
    const int lane = tid & 31;
    const int w = tid >> 5;
    const int g = lane >> 2;
    const int t = lane & 3;

    const int qb = blockIdx.x * 64;
    const int h  = blockIdx.y;
    const int b  = blockIdx.z;

    const float* qptr = g_q + (size_t)(b*HEADS + h)*SS*DH;
    const float* kptr = g_k + (size_t)(b*HEADS + h)*SS*DH;
    const float* vptr = g_v + (size_t)(b*HEADS + h)*SS*DH;

    auto issue_kv = [&](int kb, int buf) {
#pragma unroll
        for (int i = 0; i < 8; i++) {
            int idx4 = i*128 + tid;
            int r = idx4 >> 4, c4 = (idx4 & 15) * 4;
            cpa16(&Kst[buf*KST + r*LDK + c4], kptr + (size_t)(kb + r)*DH + c4);
            cpa16(&Vst[buf*VST + r*LDV + c4], vptr + (size_t)(kb + r)*DH + c4);
        }
        cpa_commit();
    };

    // prologue: async-load tile 0 into buf 0; stage Q through Kst[1]
    issue_kv(0, 0);
#pragma unroll
    for (int i = 0; i < 8; i++) {
        int idx4 = i*128 + tid;
        int r = idx4 >> 4, c4 = (idx4 & 15) * 4;
        *(uint4*)&Kst[KST + r*LDK + c4] = *(const uint4*)(qptr + (size_t)(qb + r)*DH + c4);
    }
    __syncthreads();

    unsigned qa[8][4];
#pragma unroll
    for (int ks = 0; ks < 8; ks++) {
        int base = KST + (w*16 + g)*LDK + ks*8 + t;
        qa[ks][0] = Kst[base];
        qa[ks][1] = Kst[base + 8*LDK];
        qa[ks][2] = Kst[base + 4];
        qa[ks][3] = Kst[base + 8*LDK + 4];
    }

    float o[8][4];
#pragma unroll
    for (int nf = 0; nf < 8; nf++)
#pragma unroll
        for (int i = 0; i < 4; i++) o[nf][i] = 0.f;
    float l0 = 0.f, l1 = 0.f;

    const int q0 = qb + w*16 + g;
    const int q1 = q0 + 8;
    const float* pbrow0 = pb + ((size_t)h*SS + q0)*SS;
    const float* pbrow1 = pbrow0 + (size_t)8*SS;
    const float* mrow0  = mask + ((size_t)b*SS + q0)*SS;
    const float* mrow1  = mrow0 + (size_t)8*SS;

    const int T = SS / 64;
    for (int kt = 0; kt < T; kt++) {
        const int kb = kt * 64;
        const int buf = kt & 1;

        cpa_wait<0>();
        __syncthreads();                  // tile kt visible; all warps done with
                                          // prior P (in Kst[buf]) and Q staging
        if (kt + 1 < T) issue_kv(kb + 64, buf ^ 1);

        const unsigned* Kw = Kst + buf*KST;
        const unsigned* Vw = Vst + buf*VST;

        // ---- S = Q K^T (log2-scaled domain: Q pre-scaled by log2e/8) ----
        float s[8][4];
#pragma unroll
        for (int nf = 0; nf < 8; nf++)
#pragma unroll
            for (int i = 0; i < 4; i++) s[nf][i] = 0.f;

#pragma unroll
        for (int ks = 0; ks < 8; ks++) {
#pragma unroll
            for (int nf = 0; nf < 8; nf++) {
                int base = (nf*8 + g)*LDK + ks*8 + t;
                unsigned b0 = Kw[base];
                unsigned b1 = Kw[base + 4];
                mma_tf32(s[nf], qa[ks], b0, b1, s[nf]);
            }
        }

        // ---- p = exp2(s + bias*log2e/8 + mask*log2e); l += sum(p) ----
        float rs0 = 0.f, rs1 = 0.f;
#pragma unroll
        for (int nf = 0; nf < 8; nf++) {
            int col = kb + nf*8 + 2*t;
            float2 pb0 = *(const float2*)(pbrow0 + col);
            float2 pb1 = *(const float2*)(pbrow1 + col);
            float2 mm0 = *(const float2*)(mrow0 + col);
            float2 mm1 = *(const float2*)(mrow1 + col);
            s[nf][0] = fexp2(fmaf(mm0.x, LOG2E, fmaf(pb0.x, QSCALE, s[nf][0])));
            s[nf][1] = fexp2(fmaf(mm0.y, LOG2E, fmaf(pb0.y, QSCALE, s[nf][1])));
            s[nf][2] = fexp2(fmaf(mm1.x, LOG2E, fmaf(pb1.x, QSCALE, s[nf][2])));
            s[nf][3] = fexp2(fmaf(mm1.y, LOG2E, fmaf(pb1.y, QSCALE, s[nf][3])));
            rs0 += s[nf][0] + s[nf][1];
            rs1 += s[nf][2] + s[nf][3];
        }
        l0 += rs0;
        l1 += rs1;

        // ---- all warps done reading Kst[buf] as K; reuse it for P ----
        __syncthreads();
        unsigned* Pw = Kst + buf*KST;
        {
            int pr = w*16 + g;
#pragma unroll
            for (int nf = 0; nf < 8; nf++) {
                int a0 = pr*LDK + nf*8 + 2*t;
                *(uint2*)&Pw[a0]          = make_uint2(f2tf(s[nf][0]), f2tf(s[nf][1]));
                *(uint2*)&Pw[a0 + 8*LDK]  = make_uint2(f2tf(s[nf][2]), f2tf(s[nf][3]));
            }
        }
        __syncwarp();

        // ---- O += P @ V ----
#pragma unroll
        for (int ks = 0; ks < 8; ks++) {
            unsigned pa[4];
            int base = (w*16 + g)*LDK + ks*8 + t;
            pa[0] = Pw[base];
            pa[1] = Pw[base + 8*LDK];
            pa[2] = Pw[base + 4];
            pa[3] = Pw[base + 8*LDK + 4];
#pragma unroll
            for (int nf = 0; nf < 8; nf++) {
                int vb = (ks*8 + t)*LDV + nf*8 + g;
                unsigned b0 = Vw[vb];
                unsigned b1 = Vw[vb + 4*LDV];
                mma_tf32(o[nf], pa, b0, b1, o[nf]);
            }
        }
    }

    // ---- finalize: complete the row sums (groups of 4 lanes), normalize ----
    l0 += __shfl_xor_sync(0xffffffffu, l0, 1);
    l0 += __shfl_xor_sync(0xffffffffu, l0, 2);
    l1 += __shfl_xor_sync(0xffffffffu, l1, 1);
    l1 += __shfl_xor_sync(0xffffffffu, l1, 2);
    float inv0 = 1.0f / l0, inv1 = 1.0f / l1;
#pragma unroll
    for (int nf = 0; nf < 8; nf++) {
        int d = nf*8 + 2*t;
        *(float2*)(g_ctx + ((size_t)b*SS + q0)*INNER + h*DH + d)
            = make_float2(o[nf][0]*inv0, o[nf][1]*inv0);
        *(float2*)(g_ctx + ((size_t)b*SS + q1)*INNER + h*DH + d)
            = make_float2(o[nf][2]*inv1, o[nf][3]*inv1);
    }
}

// ---------------------------------------------------------------------------
extern "C" void kernel_launch(void* const* d_in, const int* in_sizes, int n_in,
                              void* d_out, int out_size)
{
    const float* query = (const float*)d_in[0];
    const float* key   = (const float*)d_in[1];
    const float* value = (const float*)d_in[2];
    const float* mask  = (const float*)d_in[3];
    const float* pbias = (const float*)d_in[4];
    const float* Wq = (const float*)d_in[5];
    const float* bq = (const float*)d_in[6];
    const float* Wk = (const float*)d_in[7];
    const float* bk = (const float*)d_in[8];
    const float* Wv = (const float*)d_in[9];
    const float* bv = (const float*)d_in[10];
    const float* Wo = (const float*)d_in[11];
    const float* bo = (const float*)d_in[12];
    float* out = (float*)d_out;

    float* ctx_ptr = nullptr;
    cudaGetSymbolAddress((void**)&ctx_ptr, g_ctx);

    const int ATTN_SMEM = (2*KST + 2*VST) * 4;   // 71680 B
    static bool attr_set = false;
    if (!attr_set) {
        cudaFuncSetAttribute(attn_tf32_kernel,
                             cudaFuncAttributeMaxDynamicSharedMemorySize, ATTN_SMEM);
        attr_set = true;
    }

    // QKV projections
    dim3 gQKV(GN/128, (BB*SS)/128, 3);
    gemm_tf32_kernel<1><<<gQKV, 128>>>(query, key, value, Wq, Wk, Wv,
                                       bq, bk, bv, nullptr);

    // attention (proven grid order: HEADS in y, B in z)
    dim3 gAttn(SS/64, HEADS, BB);
    attn_tf32_kernel<<<gAttn, 128, ATTN_SMEM>>>(pbias, mask);

    // output projection
    dim3 gOut(GN/128, (BB*SS)/128, 1);
    gemm_tf32_kernel<0><<<gOut, 128>>>(ctx_ptr, nullptr, nullptr, Wo, nullptr, nullptr,
                                       bo, nullptr, nullptr, out);
}

// round 16
// speedup vs baseline: 1.2012x; 1.2012x over previous
#include <cuda_runtime.h>
#include <cstdint>

#define BB 2
#define SS 2048
#define HID 1024
#define HEADS 16
#define DH 64
#define INNER 1024

#define LOG2E 1.4426950408889634f
#define QSCALE (LOG2E * 0.125f)

// Scratch (device globals — no allocation allowed)
__device__ float g_q[BB*HEADS*SS*DH];    // tf32-rounded, pre-scaled by log2e/8
__device__ float g_k[BB*HEADS*SS*DH];    // tf32-rounded
__device__ float g_v[BB*HEADS*SS*DH];    // tf32-rounded
__device__ float g_ctx[BB*SS*INNER];     // [b][s][h*64+d]

// ---------------------------------------------------------------------------
// helpers
// ---------------------------------------------------------------------------
__device__ __forceinline__ unsigned f2tf(float x) {
    unsigned r;
    asm("cvt.rna.tf32.f32 %0, %1;" : "=r"(r) : "f"(x));
    return r;
}
__device__ __forceinline__ float f2tf_f(float x) {
    return __uint_as_float(f2tf(x));
}
__device__ __forceinline__ float fexp2(float x) {
    float y;
    asm("ex2.approx.ftz.f32 %0, %1;" : "=f"(y) : "f"(x));
    return y;
}
__device__ __forceinline__ void mma_tf32(float* d, const unsigned* a,
                                         unsigned b0, unsigned b1, const float* c) {
    asm volatile(
        "mma.sync.aligned.m16n8k8.row.col.f32.tf32.tf32.f32 "
        "{%0,%1,%2,%3}, {%4,%5,%6,%7}, {%8,%9}, {%10,%11,%12,%13};\n"
        : "=f"(d[0]), "=f"(d[1]), "=f"(d[2]), "=f"(d[3])
        : "r"(a[0]), "r"(a[1]), "r"(a[2]), "r"(a[3]),
          "r"(b0), "r"(b1),
          "f"(c[0]), "f"(c[1]), "f"(c[2]), "f"(c[3]));
}
__device__ __forceinline__ void cpa16(void* smem_ptr, const void* gptr) {
    unsigned sa = (unsigned)__cvta_generic_to_shared(smem_ptr);
    asm volatile("cp.async.cg.shared.global [%0], [%1], 16;\n" :: "r"(sa), "l"(gptr));
}
__device__ __forceinline__ void cpa_commit() {
    asm volatile("cp.async.commit_group;\n");
}
template<int N>
__device__ __forceinline__ void cpa_wait() {
    asm volatile("cp.async.wait_group %0;\n" :: "n"(N));
}

// ---------------------------------------------------------------------------
// GEMM (round-10 champion, unchanged): C[4096][1024] = X @ W + bias.
// ---------------------------------------------------------------------------
#define GK 1024
#define GN 1024
#define LDA 20
#define LDB 136

template<int MODE>
__global__ __launch_bounds__(128)
void gemm_tf32_kernel(const float* __restrict__ X0, const float* __restrict__ X1,
                      const float* __restrict__ X2,
                      const float* __restrict__ W0, const float* __restrict__ W1,
                      const float* __restrict__ W2,
                      const float* __restrict__ bi0, const float* __restrict__ bi1,
                      const float* __restrict__ bi2,
                      float* __restrict__ out0)
{
    __shared__ unsigned As[2][128*LDA];
    __shared__ unsigned Bs[2][16*LDB];

    const float* X; const float* W; const float* bias; float* out;
    int z = 0;
    if (MODE == 1) {
        z = blockIdx.z;
        if (z == 0)      { X = X0; W = W0; bias = bi0; out = g_q; }
        else if (z == 1) { X = X1; W = W1; bias = bi1; out = g_k; }
        else             { X = X2; W = W2; bias = bi2; out = g_v; }
    } else {
        X = X0; W = W0; bias = bi0; out = out0;
    }

    const int tid = threadIdx.x;
    const int lane = tid & 31;
    const int warp = tid >> 5;
    const int g = lane >> 2;
    const int t = lane & 3;
    const int wm = warp >> 1;
    const int wn = warp & 1;

    const int m0 = blockIdx.y * 128;
    const int n0 = blockIdx.x * 128;

    const int rowA = tid >> 2;
    const int cA   = (tid & 3) * 4;
    const int rowB = tid >> 5;
    const int cB   = (tid & 31) * 4;

    float4 ra[4], rb[4];

    auto ldg_tile = [&](int kt) {
        const int k0 = kt * 16;
#pragma unroll
        for (int p = 0; p < 4; p++)
            ra[p] = *(const float4*)(X + (size_t)(m0 + rowA + p*32) * GK + k0 + cA);
#pragma unroll
        for (int p = 0; p < 4; p++)
            rb[p] = *(const float4*)(W + (size_t)(k0 + rowB + p*4) * GN + n0 + cB);
    };
    auto sts_tile = [&](int buf) {
#pragma unroll
        for (int p = 0; p < 4; p++) {
            uint4 u = make_uint4(f2tf(ra[p].x), f2tf(ra[p].y), f2tf(ra[p].z), f2tf(ra[p].w));
            *(uint4*)&As[buf][(rowA + p*32)*LDA + cA] = u;
        }
#pragma unroll
        for (int p = 0; p < 4; p++) {
            uint4 u = make_uint4(f2tf(rb[p].x), f2tf(rb[p].y), f2tf(rb[p].z), f2tf(rb[p].w));
            *(uint4*)&Bs[buf][(rowB + p*4)*LDB + cB] = u;
        }
    };

    float c[4][8][4];
#pragma unroll
    for (int mf = 0; mf < 4; mf++)
#pragma unroll
        for (int nf = 0; nf < 8; nf++)
#pragma unroll
            for (int i = 0; i < 4; i++) c[mf][nf][i] = 0.f;

    ldg_tile(0);
    sts_tile(0);
    __syncthreads();

    for (int kt = 0; kt < GK/16; kt++) {
        const int buf = kt & 1;
        if (kt < GK/16 - 1) ldg_tile(kt + 1);

        const unsigned* A_ = As[buf];
        const unsigned* B_ = Bs[buf];
#pragma unroll
        for (int ks = 0; ks < 2; ks++) {
            unsigned a[4][4];
#pragma unroll
            for (int mf = 0; mf < 4; mf++) {
                int base = (wm*64 + mf*16 + g)*LDA + ks*8 + t;
                a[mf][0] = A_[base];
                a[mf][1] = A_[base + 8*LDA];
                a[mf][2] = A_[base + 4];
                a[mf][3] = A_[base + 8*LDA + 4];
            }
            unsigned bf[8][2];
#pragma unroll
            for (int nf = 0; nf < 8; nf++) {
                int base = (ks*8 + t)*LDB + wn*64 + nf*8 + g;
                bf[nf][0] = B_[base];
                bf[nf][1] = B_[base + 4*LDB];
            }
#pragma unroll
            for (int mf = 0; mf < 4; mf++)
#pragma unroll
                for (int nf = 0; nf < 8; nf++)
                    mma_tf32(c[mf][nf], a[mf], bf[nf][0], bf[nf][1], c[mf][nf]);
        }

        if (kt < GK/16 - 1) {
            sts_tile((kt + 1) & 1);
            __syncthreads();
        }
    }

    // epilogue
#pragma unroll
    for (int mf = 0; mf < 4; mf++) {
        int r0 = m0 + wm*64 + mf*16 + g;
        int r1 = r0 + 8;
#pragma unroll
        for (int nf = 0; nf < 8; nf++) {
            int col = n0 + wn*64 + nf*8 + 2*t;
            float2 bs = *(const float2*)(bias + col);
            float v00 = c[mf][nf][0] + bs.x, v01 = c[mf][nf][1] + bs.y;
            float v10 = c[mf][nf][2] + bs.x, v11 = c[mf][nf][3] + bs.y;
            if (MODE == 1) {
                if (z == 0) { v00 *= QSCALE; v01 *= QSCALE; v10 *= QSCALE; v11 *= QSCALE; }
                v00 = f2tf_f(v00); v01 = f2tf_f(v01);
                v10 = f2tf_f(v10); v11 = f2tf_f(v11);
                int h = col >> 6, d = col & 63;
                int b0i = r0 >> 11, s0 = r0 & 2047;
                int b1i = r1 >> 11, s1 = r1 & 2047;
                *(float2*)(out + ((size_t)(b0i*HEADS + h)*SS + s0)*DH + d) = make_float2(v00, v01);
                *(float2*)(out + ((size_t)(b1i*HEADS + h)*SS + s1)*DH + d) = make_float2(v10, v11);
            } else {
                *(float2*)(out + (size_t)r0*GN + col) = make_float2(v00, v01);
                *(float2*)(out + (size_t)r1*GN + col) = make_float2(v10, v11);
            }
        }
    }
}

// ---------------------------------------------------------------------------
// Flash attention: 128 q-rows/CTA with 128 threads (two 64-row q-halves per
// warp set), tf32 mma, champion softmax (online, exp2-domain), cp.async
// double-buffered K/V; both P halves serially reuse the consumed K stage.
// grid: (S/128, HEADS, B). smem 71680 B -> 3 CTAs/SM.
// ---------------------------------------------------------------------------
#define LDK 68
#define LDV 72
#define KST (64*LDK)
#define VST (64*LDV)

__global__ __launch_bounds__(128)
void attn_tf32_kernel(const float* __restrict__ pb, const float* __restrict__ mask)
{
    extern __shared__ unsigned smx[];
    unsigned* Kst = smx;             // [2][64*LDK]
    unsigned* Vst = smx + 2*KST;     // [2][64*LDV]

    const int tid = threadIdx.x;
    const int lane = tid & 31;
    const int w = tid >> 5;
    const int g = lane >> 2;
    const int t = lane & 3;

    const int qb = blockIdx.x * 128;
    const int h  = blockIdx.y;
    const int b  = blockIdx.z;

    const float* qptr = g_q + (size_t)(b*HEADS + h)*SS*DH;
    const float* kptr = g_k + (size_t)(b*HEADS + h)*SS*DH;
    const float* vptr = g_v + (size_t)(b*HEADS + h)*SS*DH;

    auto issue_kv = [&](int kb, int buf) {
#pragma unroll
        for (int i = 0; i < 8; i++) {
            int idx4 = i*128 + tid;
            int r = idx4 >> 4, c4 = (idx4 & 15) * 4;
            cpa16(&Kst[buf*KST + r*LDK + c4], kptr + (size_t)(kb + r)*DH + c4);
            cpa16(&Vst[buf*VST + r*LDV + c4], vptr + (size_t)(kb + r)*DH + c4);
        }
        cpa_commit();
    };

    // prologue: async-load K/V tile 0 into buf 0;
    // stage Q rows 0-63 in Kst[1], rows 64-127 in Vst[1]
    issue_kv(0, 0);
#pragma unroll
    for (int i = 0; i < 8; i++) {
        int idx4 = i*128 + tid;
        int r = idx4 >> 4, c4 = (idx4 & 15) * 4;
        *(uint4*)&Kst[KST + r*LDK + c4] = *(const uint4*)(qptr + (size_t)(qb + r)*DH + c4);
        *(uint4*)&Vst[VST + r*LDV + c4] = *(const uint4*)(qptr + (size_t)(qb + 64 + r)*DH + c4);
    }
    __syncthreads();

    unsigned qaA[8][4], qaB[8][4];
#pragma unroll
    for (int ks = 0; ks < 8; ks++) {
        int baseA = KST + (w*16 + g)*LDK + ks*8 + t;
        qaA[ks][0] = Kst[baseA];
        qaA[ks][1] = Kst[baseA + 8*LDK];
        qaA[ks][2] = Kst[baseA + 4];
        qaA[ks][3] = Kst[baseA + 8*LDK + 4];
        int baseB = VST + (w*16 + g)*LDV + ks*8 + t;
        qaB[ks][0] = Vst[baseB];
        qaB[ks][1] = Vst[baseB + 8*LDV];
        qaB[ks][2] = Vst[baseB + 4];
        qaB[ks][3] = Vst[baseB + 8*LDV + 4];
    }

    float oA[8][4], oB[8][4];
#pragma unroll
    for (int nf = 0; nf < 8; nf++)
#pragma unroll
        for (int i = 0; i < 4; i++) { oA[nf][i] = 0.f; oB[nf][i] = 0.f; }
    float mA0 = -1e30f, mA1 = -1e30f, lA0 = 0.f, lA1 = 0.f;
    float mB0 = -1e30f, mB1 = -1e30f, lB0 = 0.f, lB1 = 0.f;

    const int q0 = qb + w*16 + g;        // half A rows: q0, q0+8
    const size_t pbase = (size_t)h*SS*SS + (size_t)q0*SS;
    const size_t mbase = (size_t)b*SS*SS + (size_t)q0*SS;

    const int T = SS / 64;
    for (int kt = 0; kt < T; kt++) {
        const int kb = kt * 64;
        const int buf = kt & 1;

        cpa_wait<0>();
        __syncthreads();                  // tile kt visible; all warps past kt-1
        if (kt + 1 < T) issue_kv(kb + 64, buf ^ 1);

        const unsigned* Kw = Kst + buf*KST;
        const unsigned* Vw = Vst + buf*VST;

        float sA[8][4], sB[8][4];
#pragma unroll
        for (int nf = 0; nf < 8; nf++)
#pragma unroll
            for (int i = 0; i < 4; i++) { sA[nf][i] = 0.f; sB[nf][i] = 0.f; }

        // ---- S_A = Q_A K^T ----
#pragma unroll
        for (int ks = 0; ks < 8; ks++) {
#pragma unroll
            for (int nf = 0; nf < 8; nf++) {
                int base = (nf*8 + g)*LDK + ks*8 + t;
                mma_tf32(sA[nf], qaA[ks], Kw[base], Kw[base + 4], sA[nf]);
            }
        }
        // ---- bias/mask + online softmax for A ----
#pragma unroll
        for (int nf = 0; nf < 8; nf++) {
            int col = kb + nf*8 + 2*t;
            float2 pb0 = *(const float2*)(pb + pbase + col);
            float2 pb1 = *(const float2*)(pb + pbase + 8*SS + col);
            float2 mm0 = *(const float2*)(mask + mbase + col);
            float2 mm1 = *(const float2*)(mask + mbase + 8*SS + col);
            sA[nf][0] = fmaf(mm0.x, LOG2E, fmaf(pb0.x, QSCALE, sA[nf][0]));
            sA[nf][1] = fmaf(mm0.y, LOG2E, fmaf(pb0.y, QSCALE, sA[nf][1]));
            sA[nf][2] = fmaf(mm1.x, LOG2E, fmaf(pb1.x, QSCALE, sA[nf][2]));
            sA[nf][3] = fmaf(mm1.y, LOG2E, fmaf(pb1.y, QSCALE, sA[nf][3]));
        }
        {
            float mx0 = -1e30f, mx1 = -1e30f;
#pragma unroll
            for (int nf = 0; nf < 8; nf++) {
                mx0 = fmaxf(mx0, fmaxf(sA[nf][0], sA[nf][1]));
                mx1 = fmaxf(mx1, fmaxf(sA[nf][2], sA[nf][3]));
            }
            mx0 = fmaxf(mx0, __shfl_xor_sync(0xffffffffu, mx0, 1));
            mx0 = fmaxf(mx0, __shfl_xor_sync(0xffffffffu, mx0, 2));
            mx1 = fmaxf(mx1, __shfl_xor_sync(0xffffffffu, mx1, 1));
            mx1 = fmaxf(mx1, __shfl_xor_sync(0xffffffffu, mx1, 2));
            float nm0 = fmaxf(mA0, mx0), nm1 = fmaxf(mA1, mx1);
            float c0 = fexp2(mA0 - nm0), c1 = fexp2(mA1 - nm1);
            mA0 = nm0; mA1 = nm1;
            float rs0 = 0.f, rs1 = 0.f;
#pragma unroll
            for (int nf = 0; nf < 8; nf++) {
                sA[nf][0] = fexp2(sA[nf][0] - nm0);
                sA[nf][1] = fexp2(sA[nf][1] - nm0);
                sA[nf][2] = fexp2(sA[nf][2] - nm1);
                sA[nf][3] = fexp2(sA[nf][3] - nm1);
                rs0 += sA[nf][0] + sA[nf][1];
                rs1 += sA[nf][2] + sA[nf][3];
            }
            rs0 += __shfl_xor_sync(0xffffffffu, rs0, 1);
            rs0 += __shfl_xor_sync(0xffffffffu, rs0, 2);
            rs1 += __shfl_xor_sync(0xffffffffu, rs1, 1);
            rs1 += __shfl_xor_sync(0xffffffffu, rs1, 2);
            lA0 = lA0*c0 + rs0;
            lA1 = lA1*c1 + rs1;
#pragma unroll
            for (int nf = 0; nf < 8; nf++) {
                oA[nf][0] *= c0; oA[nf][1] *= c0;
                oA[nf][2] *= c1; oA[nf][3] *= c1;
            }
        }

        // ---- S_B = Q_B K^T ----
#pragma unroll
        for (int ks = 0; ks < 8; ks++) {
#pragma unroll
            for (int nf = 0; nf < 8; nf++) {
                int base = (nf*8 + g)*LDK + ks*8 + t;
                mma_tf32(sB[nf], qaB[ks], Kw[base], Kw[base + 4], sB[nf]);
            }
        }
        // ---- bias/mask + online softmax for B (rows q0+64) ----
#pragma unroll
        for (int nf = 0; nf < 8; nf++) {
            int col = kb + nf*8 + 2*t;
            float2 pb0 = *(const float2*)(pb + pbase + (size_t)64*SS + col);
            float2 pb1 = *(const float2*)(pb + pbase + (size_t)72*SS + col);
            float2 mm0 = *(const float2*)(mask + mbase + (size_t)64*SS + col);
            float2 mm1 = *(const float2*)(mask + mbase + (size_t)72*SS + col);
            sB[nf][0] = fmaf(mm0.x, LOG2E, fmaf(pb0.x, QSCALE, sB[nf][0]));
            sB[nf][1] = fmaf(mm0.y, LOG2E, fmaf(pb0.y, QSCALE, sB[nf][1]));
            sB[nf][2] = fmaf(mm1.x, LOG2E, fmaf(pb1.x, QSCALE, sB[nf][2]));
            sB[nf][3] = fmaf(mm1.y, LOG2E, fmaf(pb1.y, QSCALE, sB[nf][3]));
        }
        {
            float mx0 = -1e30f, mx1 = -1e30f;
#pragma unroll
            for (int nf = 0; nf < 8; nf++) {
                mx0 = fmaxf(mx0, fmaxf(sB[nf][0], sB[nf][1]));
                mx1 = fmaxf(mx1, fmaxf(sB[nf][2], sB[nf][3]));
            }
            mx0 = fmaxf(mx0, __shfl_xor_sync(0xffffffffu, mx0, 1));
            mx0 = fmaxf(mx0, __shfl_xor_sync(0xffffffffu, mx0, 2));
            mx1 = fmaxf(mx1, __shfl_xor_sync(0xffffffffu, mx1, 1));
            mx1 = fmaxf(mx1, __shfl_xor_sync(0xffffffffu, mx1, 2));
            float nm0 = fmaxf(mB0, mx0), nm1 = fmaxf(mB1, mx1);
            float c0 = fexp2(mB0 - nm0), c1 = fexp2(mB1 - nm1);
            mB0 = nm0; mB1 = nm1;
            float rs0 = 0.f, rs1 = 0.f;
#pragma unroll
            for (int nf = 0; nf < 8; nf++) {
                sB[nf][0] = fexp2(sB[nf][0] - nm0);
                sB[nf][1] = fexp2(sB[nf][1] - nm0);
                sB[nf][2] = fexp2(sB[nf][2] - nm1);
                sB[nf][3] = fexp2(sB[nf][3] - nm1);
                rs0 += sB[nf][0] + sB[nf][1];
                rs1 += sB[nf][2] + sB[nf][3];
            }
            rs0 += __shfl_xor_sync(0xffffffffu, rs0, 1);
            rs0 += __shfl_xor_sync(0xffffffffu, rs0, 2);
            rs1 += __shfl_xor_sync(0xffffffffu, rs1, 1);
            rs1 += __shfl_xor_sync(0xffffffffu, rs1, 2);
            lB0 = lB0*c0 + rs0;
            lB1 = lB1*c1 + rs1;
#pragma unroll
            for (int nf = 0; nf < 8; nf++) {
                oB[nf][0] *= c0; oB[nf][1] *= c0;
                oB[nf][2] *= c1; oB[nf][3] *= c1;
            }
        }

        // ---- all warps done reading Kst[buf] as K; reuse it for P ----
        __syncthreads();
        unsigned* Pw = Kst + buf*KST;
        const int pr = w*16 + g;
        // P_A -> PV_A
#pragma unroll
        for (int nf = 0; nf < 8; nf++) {
            int a0 = pr*LDK + nf*8 + 2*t;
            *(uint2*)&Pw[a0]          = make_uint2(f2tf(sA[nf][0]), f2tf(sA[nf][1]));
            *(uint2*)&Pw[a0 + 8*LDK]  = make_uint2(f2tf(sA[nf][2]), f2tf(sA[nf][3]));
        }
        __syncwarp();
#pragma unroll
        for (int ks = 0; ks < 8; ks++) {
            unsigned pa[4];
            int base = pr*LDK + ks*8 + t;
            pa[0] = Pw[base];
            pa[1] = Pw[base + 8*LDK];
            pa[2] = Pw[base + 4];
            pa[3] = Pw[base + 8*LDK + 4];
#pragma unroll
            for (int nf = 0; nf < 8; nf++) {
                int vb = (ks*8 + t)*LDV + nf*8 + g;
                mma_tf32(oA[nf], pa, Vw[vb], Vw[vb + 4*LDV], oA[nf]);
            }
        }
        __syncwarp();
        // P_B -> PV_B (same per-warp-private rows)
#pragma unroll
        for (int nf = 0; nf < 8; nf++) {
            int a0 = pr*LDK + nf*8 + 2*t;
            *(uint2*)&Pw[a0]          = make_uint2(f2tf(sB[nf][0]), f2tf(sB[nf][1]));
            *(uint2*)&Pw[a0 + 8*LDK]  = make_uint2(f2tf(sB[nf][2]), f2tf(sB[nf][3]));
        }
        __syncwarp();
#pragma unroll
        for (int ks = 0; ks < 8; ks++) {
            unsigned pa[4];
            int base = pr*LDK + ks*8 + t;
            pa[0] = Pw[base];
            pa[1] = Pw[base + 8*LDK];
            pa[2] = Pw[base + 4];
            pa[3] = Pw[base + 8*LDK + 4];
#pragma unroll
            for (int nf = 0; nf < 8; nf++) {
                int vb = (ks*8 + t)*LDV + nf*8 + g;
                mma_tf32(oB[nf], pa, Vw[vb], Vw[vb + 4*LDV], oB[nf]);
            }
        }
    }

    // ---- finalize ----
    float iA0 = 1.0f / lA0, iA1 = 1.0f / lA1;
    float iB0 = 1.0f / lB0, iB1 = 1.0f / lB1;
#pragma unroll
    for (int nf = 0; nf < 8; nf++) {
        int d = nf*8 + 2*t;
        float* base0 = g_ctx + ((size_t)b*SS + q0)*INNER + h*DH + d;
        *(float2*)(base0)                      = make_float2(oA[nf][0]*iA0, oA[nf][1]*iA0);
        *(float2*)(base0 + (size_t)8*INNER)    = make_float2(oA[nf][2]*iA1, oA[nf][3]*iA1);
        *(float2*)(base0 + (size_t)64*INNER)   = make_float2(oB[nf][0]*iB0, oB[nf][1]*iB0);
        *(float2*)(base0 + (size_t)72*INNER)   = make_float2(oB[nf][2]*iB1, oB[nf][3]*iB1);
    }
}

// ---------------------------------------------------------------------------
extern "C" void kernel_launch(void* const* d_in, const int* in_sizes, int n_in,
                              void* d_out, int out_size)
{
    const float* query = (const float*)d_in[0];
    const float* key   = (const float*)d_in[1];
    const float* value = (const float*)d_in[2];
    const float* mask  = (const float*)d_in[3];
    const float* pbias = (const float*)d_in[4];
    const float* Wq = (const float*)d_in[5];
    const float* bq = (const float*)d_in[6];
    const float* Wk = (const float*)d_in[7];
    const float* bk = (const float*)d_in[8];
    const float* Wv = (const float*)d_in[9];
    const float* bv = (const float*)d_in[10];
    const float* Wo = (const float*)d_in[11];
    const float* bo = (const float*)d_in[12];
    float* out = (float*)d_out;

    float* ctx_ptr = nullptr;
    cudaGetSymbolAddress((void**)&ctx_ptr, g_ctx);

    const int ATTN_SMEM = (2*KST + 2*VST) * 4;   // 71680 B
    static bool attr_set = false;
    if (!attr_set) {
        cudaFuncSetAttribute(attn_tf32_kernel,
                             cudaFuncAttributeMaxDynamicSharedMemorySize, ATTN_SMEM);
        attr_set = true;
    }

    // QKV projections
    dim3 gQKV(GN/128, (BB*SS)/128, 3);
    gemm_tf32_kernel<1><<<gQKV, 128>>>(query, key, value, Wq, Wk, Wv,
                                       bq, bk, bv, nullptr);

    // attention (128 q-rows per 128-thread CTA)
    dim3 gAttn(SS/128, HEADS, BB);
    attn_tf32_kernel<<<gAttn, 128, ATTN_SMEM>>>(pbias, mask);

    // output projection
    dim3 gOut(GN/128, (BB*SS)/128, 1);
    gemm_tf32_kernel<0><<<gOut, 128>>>(ctx_ptr, nullptr, nullptr, Wo, nullptr, nullptr,
                                       bo, nullptr, nullptr, out);
}